// round 3
// baseline (speedup 1.0000x reference)
#include <cuda_runtime.h>
#include <cuda_fp16.h>
#include <cuda_bf16.h>
#include <math.h>
#include <type_traits>

// ---------------------------------------------------------------------------
// GATLayers: 2x (GATConv -> BatchNorm -> ReLU).  N=20000, E=640000, H=2
// Round-3:
//   - scores via precomputed att-vectors: a_s = x @ (W . att_src)  (exact)
//   - GEMM: f32x2 FMA, 4-kk batched float4 smem reads (FFMA-bound)
//   - agg: warp/node both heads, single-pass softmax, 1-deep row prefetch
//   - CSR: rank-in-histogram, atomic-free scatter
//   - BN: 400-block stats, layer-1 BN+ReLU fused into consumers
// ---------------------------------------------------------------------------

constexpr int NN = 20000;
constexpr int EE = 640000;
constexpr int FF = 64;
constexpr int D1 = 128;
constexpr int D2 = 256;

// ------------------------------ scratch ------------------------------------
__device__ int    g_is64;
__device__ int    g_deg[NN];
__device__ int    g_rowptr[NN + 1];
__device__ int    g_rank[EE];
__device__ int    g_col[EE];
__device__ __half g_hx1[NN * D1];
__device__ float  g_as1[NN * 2];
__device__ float  g_ad1[NN * 2];
__device__ float  g_out1[NN * D1];
__device__ __half g_hx2[NN * D2];
__device__ float  g_as2[NN * 2];
__device__ float  g_ad2[NN * 2];
__device__ float  g_out2[NN * D2];
__device__ float  g_part[400 * 2 * 256];
__device__ float  g_scale[256];
__device__ float  g_shift[256];
__device__ float4 g_u1[64];    // per-feature (us_h0, us_h1, ud_h0, ud_h1)
__device__ float4 g_u2[128];

// --------------------------- f32x2 helpers ----------------------------------
__device__ __forceinline__ unsigned long long pack2(float lo, float hi) {
    unsigned long long r;
    asm("mov.b64 %0, {%1, %2};" : "=l"(r)
        : "r"(__float_as_uint(lo)), "r"(__float_as_uint(hi)));
    return r;
}
__device__ __forceinline__ void unpk2(unsigned long long v, float& x, float& y) {
    unsigned a, b;
    asm("mov.b64 {%0, %1}, %2;" : "=r"(a), "=r"(b) : "l"(v));
    x = __uint_as_float(a); y = __uint_as_float(b);
}
__device__ __forceinline__ void ffma2(unsigned long long& d,
                                      unsigned long long a,
                                      unsigned long long b) {
    asm("fma.rn.f32x2 %0, %1, %2, %0;" : "+l"(d) : "l"(a), "l"(b));
}

// -------------------------- CSR construction -------------------------------
__global__ void zero_detect_kernel(const int* __restrict__ ei32) {
    int i = blockIdx.x * blockDim.x + threadIdx.x;
    if (i < NN) g_deg[i] = 0;
    if (i == 0) {
        int is64 = 1;
        for (int k = 0; k < 64; k++)
            if (ei32[2 * k + 1] != 0) { is64 = 0; break; }
        g_is64 = is64;
    }
}

__device__ __forceinline__ int edge_val(const void* ei, int idx, int is64) {
    if (is64) return (int)((const long long*)ei)[idx];
    return ((const int*)ei)[idx];
}

__global__ void hist_kernel(const void* __restrict__ ei) {
    int e = blockIdx.x * blockDim.x + threadIdx.x;
    if (e >= EE) return;
    int dst = edge_val(ei, EE + e, g_is64);
    g_rank[e] = atomicAdd(&g_deg[dst], 1);
}

__global__ __launch_bounds__(1024) void scan_kernel() {
    __shared__ int s[1024];
    const int t = threadIdx.x;
    const int chunk = (NN + 1023) / 1024;  // 20
    int lo = t * chunk;
    int hi = lo + chunk; if (hi > NN) hi = NN;
    if (lo > NN) lo = NN;
    int sum = 0;
    for (int i = lo; i < hi; i++) sum += g_deg[i];
    s[t] = sum;
    __syncthreads();
    for (int off = 1; off < 1024; off <<= 1) {
        int v = (t >= off) ? s[t - off] : 0;
        __syncthreads();
        s[t] += v;
        __syncthreads();
    }
    int run = s[t] - sum;
    for (int i = lo; i < hi; i++) {
        g_rowptr[i] = run;
        run += g_deg[i];
    }
    if (t == 1023) g_rowptr[NN] = s[1023];
}

__global__ void scatter_kernel(const void* __restrict__ ei) {
    int e = blockIdx.x * blockDim.x + threadIdx.x;
    if (e >= EE) return;
    int is64 = g_is64;
    int src = edge_val(ei, e, is64);
    int dst = edge_val(ei, EE + e, is64);
    g_col[g_rowptr[dst] + g_rank[e]] = src;
}

// ----------------------- attention vector precompute ------------------------
// u[f] = (W[f,h0]·att_src_h0, W[f,h1]·att_src_h1, W[f,h0]·att_dst_h0, ...)
__global__ void attvec_kernel(const float* __restrict__ W1,
                              const float* __restrict__ s1,
                              const float* __restrict__ d1,
                              const float* __restrict__ W2,
                              const float* __restrict__ s2,
                              const float* __restrict__ d2) {
    int t = threadIdx.x;  // 192 threads
    if (t < 64) {
        int f = t;
        float4 u = make_float4(0.f, 0.f, 0.f, 0.f);
        for (int c = 0; c < 64; c++) {
            float w0 = W1[f * 128 + c], w1 = W1[f * 128 + 64 + c];
            u.x += w0 * s1[c];      u.y += w1 * s1[64 + c];
            u.z += w0 * d1[c];      u.w += w1 * d1[64 + c];
        }
        g_u1[f] = u;
    } else if (t < 192) {
        int f = t - 64;
        float4 u = make_float4(0.f, 0.f, 0.f, 0.f);
        for (int c = 0; c < 128; c++) {
            float w0 = W2[f * 256 + c], w1 = W2[f * 256 + 128 + c];
            u.x += w0 * s2[c];      u.y += w1 * s2[128 + c];
            u.z += w0 * d2[c];      u.w += w1 * d2[128 + c];
        }
        g_u2[f] = u;
    }
}

// --------------------------- score GEMV -------------------------------------
// One warp per node: (s0,s1,d0,d1) = sum_f A[n,f] * u[f]. BN: apply layer-1
// BN+ReLU to A on the fly.
template <int K, bool BN>
__global__ __launch_bounds__(256) void gemv_kernel(
    const float* __restrict__ A, const float4* __restrict__ U,
    float* __restrict__ as_out, float* __restrict__ ad_out)
{
    const int lane = threadIdx.x & 31;
    const int warp = threadIdx.x >> 5;
    const int node = blockIdx.x * 8 + warp;
    float4 acc = make_float4(0.f, 0.f, 0.f, 0.f);
    #pragma unroll
    for (int f = lane; f < K; f += 32) {
        float v = A[(size_t)node * K + f];
        if (BN) { v = v * g_scale[f] + g_shift[f]; v = v > 0.f ? v : 0.f; }
        float4 u = U[f];
        acc.x += v * u.x; acc.y += v * u.y;
        acc.z += v * u.z; acc.w += v * u.w;
    }
    #pragma unroll
    for (int o = 16; o; o >>= 1) {
        acc.x += __shfl_xor_sync(0xffffffffu, acc.x, o);
        acc.y += __shfl_xor_sync(0xffffffffu, acc.y, o);
        acc.z += __shfl_xor_sync(0xffffffffu, acc.z, o);
        acc.w += __shfl_xor_sync(0xffffffffu, acc.w, o);
    }
    if (lane == 0) {
        as_out[node * 2 + 0] = acc.x;
        as_out[node * 2 + 1] = acc.y;
        ad_out[node * 2 + 0] = acc.z;
        ad_out[node * 2 + 1] = acc.w;
    }
}

// ------------------------------- GEMM --------------------------------------
// C[M,Ncol] = A[M,K] @ B[K,Ncol], fp32 f32x2 FMA, half out.
// BM=64, BN=128, BK=32, 256 threads, 8x4 per thread, 4-kk batched reads.
template <bool BN_A>
__global__ __launch_bounds__(256) void gemm_kernel(
    const float* __restrict__ A, const float* __restrict__ B,
    __half* __restrict__ C, int M, int K, int Ncol)
{
    __shared__ float As[64 * 32];
    __shared__ float Bs[32 * 128];
    const int tid = threadIdx.x;
    const int row0 = blockIdx.x * 64;
    const int col0 = blockIdx.y * 128;
    const int tx = tid & 31;
    const int ty = tid >> 5;
    unsigned long long acc[8][2];
    #pragma unroll
    for (int i = 0; i < 8; i++) { acc[i][0] = 0ull; acc[i][1] = 0ull; }

    for (int k0 = 0; k0 < K; k0 += 32) {
        float sc = 1.f, sh = 0.f;
        if (BN_A) { sc = g_scale[k0 + tx]; sh = g_shift[k0 + tx]; }
        #pragma unroll
        for (int i = 0; i < 8; i++) {
            int idx = tid + i * 256;
            int r = idx >> 5, c = idx & 31;     // c == tx
            int gr = row0 + r;
            float v = (gr < M) ? A[(size_t)gr * K + k0 + c] : 0.f;
            if (BN_A) { v = v * sc + sh; v = v > 0.f ? v : 0.f; }
            As[idx] = v;
        }
        #pragma unroll
        for (int i = 0; i < 16; i++) {
            int idx = tid + i * 256;
            int r = idx >> 7, c = idx & 127;
            Bs[idx] = B[(size_t)(k0 + r) * Ncol + col0 + c];
        }
        __syncthreads();
        #pragma unroll
        for (int kk = 0; kk < 32; kk += 4) {
            ulonglong2 b0 = *(const ulonglong2*)&Bs[(kk + 0) * 128 + tx * 4];
            ulonglong2 b1 = *(const ulonglong2*)&Bs[(kk + 1) * 128 + tx * 4];
            ulonglong2 b2 = *(const ulonglong2*)&Bs[(kk + 2) * 128 + tx * 4];
            ulonglong2 b3 = *(const ulonglong2*)&Bs[(kk + 3) * 128 + tx * 4];
            #pragma unroll
            for (int i = 0; i < 8; i++) {
                float4 a4 = *(const float4*)&As[(ty * 8 + i) * 32 + kk];
                unsigned long long a0 = pack2(a4.x, a4.x);
                unsigned long long a1 = pack2(a4.y, a4.y);
                unsigned long long a2 = pack2(a4.z, a4.z);
                unsigned long long a3 = pack2(a4.w, a4.w);
                ffma2(acc[i][0], a0, b0.x); ffma2(acc[i][1], a0, b0.y);
                ffma2(acc[i][0], a1, b1.x); ffma2(acc[i][1], a1, b1.y);
                ffma2(acc[i][0], a2, b2.x); ffma2(acc[i][1], a2, b2.y);
                ffma2(acc[i][0], a3, b3.x); ffma2(acc[i][1], a3, b3.y);
            }
        }
        __syncthreads();
    }
    #pragma unroll
    for (int i = 0; i < 8; i++) {
        int gr = row0 + ty * 8 + i;
        if (gr < M) {
            float c0, c1, c2, c3;
            unpk2(acc[i][0], c0, c1);
            unpk2(acc[i][1], c2, c3);
            __half2 h0 = __floats2half2_rn(c0, c1);
            __half2 h1 = __floats2half2_rn(c2, c3);
            uint2 st;
            st.x = *(unsigned*)&h0;
            st.y = *(unsigned*)&h1;
            *(uint2*)(C + (size_t)gr * Ncol + col0 + tx * 4) = st;
        }
    }
}

// ------------------- segment softmax + weighted aggregate ------------------
// One warp per node, both heads, single-pass (scores O(1): exp safe, p/z
// shift-invariant). 1-deep prefetch of next edge's (as, row).
template <int C>
__global__ __launch_bounds__(256) void agg_kernel(
    const __half* __restrict__ hx, const float* __restrict__ as,
    const float* __restrict__ ad, const float* __restrict__ bias,
    float* __restrict__ out)
{
    const int lane = threadIdx.x & 31;
    const int warp = threadIdx.x >> 5;
    const int node = blockIdx.x * 8 + warp;
    constexpr int D = 2 * C;
    constexpr int V = D / 32;  // 4 or 8 halves per lane
    using RowT = typename std::conditional<V == 4, uint2, uint4>::type;
    const int base = g_rowptr[node];
    const int deg = g_rowptr[node + 1] - base;
    const float2* as2 = (const float2*)as;
    const float2 adi = ((const float2*)ad)[node];

    float acc[V];
    #pragma unroll
    for (int v = 0; v < V; v++) acc[v] = 0.f;
    float z0, z1;

    auto accum = [&](RowT u, float p) {
        if constexpr (V == 4) {
            float2 f0 = __half22float2(*(__half2*)&u.x);
            float2 f1 = __half22float2(*(__half2*)&u.y);
            acc[0] += p * f0.x; acc[1] += p * f0.y;
            acc[2] += p * f1.x; acc[3] += p * f1.y;
        } else {
            float2 f0 = __half22float2(*(__half2*)&u.x);
            float2 f1 = __half22float2(*(__half2*)&u.y);
            float2 f2 = __half22float2(*(__half2*)&u.z);
            float2 f3 = __half22float2(*(__half2*)&u.w);
            acc[0] += p * f0.x; acc[1] += p * f0.y;
            acc[2] += p * f1.x; acc[3] += p * f1.y;
            acc[4] += p * f2.x; acc[5] += p * f2.y;
            acc[6] += p * f3.x; acc[7] += p * f3.y;
        }
    };

    {   // self loop
        float2 a = as2[node];
        float e0 = a.x + adi.x; e0 = e0 > 0.f ? e0 : 0.2f * e0;
        float e1 = a.y + adi.y; e1 = e1 > 0.f ? e1 : 0.2f * e1;
        float p0 = __expf(e0), p1 = __expf(e1);
        z0 = p0; z1 = p1;
        RowT u = *(const RowT*)(hx + (size_t)node * D + lane * V);
        accum(u, (lane < 16) ? p0 : p1);
    }

    if (deg > 0) {
        int s = g_col[base];
        float2 a_n = as2[s];
        RowT u_n = *(const RowT*)(hx + (size_t)s * D + lane * V);
        for (int j = 0; j < deg; j++) {
            float2 a = a_n;
            RowT u = u_n;
            if (j + 1 < deg) {
                int s2 = g_col[base + j + 1];
                a_n = as2[s2];
                u_n = *(const RowT*)(hx + (size_t)s2 * D + lane * V);
            }
            float e0 = a.x + adi.x; e0 = e0 > 0.f ? e0 : 0.2f * e0;
            float e1 = a.y + adi.y; e1 = e1 > 0.f ? e1 : 0.2f * e1;
            float p0 = __expf(e0), p1 = __expf(e1);
            z0 += p0; z1 += p1;
            accum(u, (lane < 16) ? p0 : p1);
        }
    }

    const float inv = 1.f / ((lane < 16) ? z0 : z1);
    float* o = out + (size_t)node * D + lane * V;
    const float* b = bias + lane * V;
    #pragma unroll
    for (int v = 0; v < V; v++) o[v] = acc[v] * inv + b[v];
}

// ------------------------------ batch norm ----------------------------------
__global__ void bnstats_kernel(const float* __restrict__ X, int COLS) {
    const int c = threadIdx.x;          // blockDim.x == COLS
    const int r0 = blockIdx.x * 50;     // 400 blocks * 50 rows
    float s = 0.f, q = 0.f;
    for (int r = r0; r < r0 + 50; r++) {
        float v = X[(size_t)r * COLS + c];
        s += v;
        q += v * v;
    }
    g_part[blockIdx.x * 2 * COLS + c] = s;
    g_part[blockIdx.x * 2 * COLS + COLS + c] = q;
}

__global__ void bnfin_kernel(const float* __restrict__ gamma,
                             const float* __restrict__ beta, int COLS) {
    const int c = threadIdx.x;
    float s = 0.f, q = 0.f;
    for (int b = 0; b < 400; b++) {
        s += g_part[b * 2 * COLS + c];
        q += g_part[b * 2 * COLS + COLS + c];
    }
    const float mu = s * (1.f / NN);
    const float var = q * (1.f / NN) - mu * mu;
    const float sc = gamma[c] * rsqrtf(var + 1e-5f);
    g_scale[c] = sc;
    g_shift[c] = beta[c] - mu * sc;
}

__global__ void bnapply_kernel(const float* __restrict__ X,
                               float* __restrict__ Y, int mask, int total) {
    int i = blockIdx.x * blockDim.x + threadIdx.x;
    if (i >= total) return;
    int c = i & mask;
    float y = X[i] * g_scale[c] + g_shift[c];
    Y[i] = y > 0.f ? y : 0.f;
}

// ------------------------------- launcher -----------------------------------
extern "C" void kernel_launch(void* const* d_in, const int* in_sizes, int n_in,
                              void* d_out, int out_size) {
    const float* x        = (const float*)d_in[0];
    const void*  ei       = d_in[1];
    const float* W1       = (const float*)d_in[2];
    const float* att_src1 = (const float*)d_in[3];
    const float* att_dst1 = (const float*)d_in[4];
    const float* bias1    = (const float*)d_in[5];
    const float* gamma1   = (const float*)d_in[6];
    const float* beta1    = (const float*)d_in[7];
    const float* W2       = (const float*)d_in[8];
    const float* att_src2 = (const float*)d_in[9];
    const float* att_dst2 = (const float*)d_in[10];
    const float* bias2    = (const float*)d_in[11];
    const float* gamma2   = (const float*)d_in[12];
    const float* beta2    = (const float*)d_in[13];
    float* out = (float*)d_out;

    __half *hx1, *hx2;
    float *as1, *ad1, *out1, *as2, *ad2, *out2;
    float4 *u1, *u2;
    cudaGetSymbolAddress((void**)&hx1,  g_hx1);
    cudaGetSymbolAddress((void**)&as1,  g_as1);
    cudaGetSymbolAddress((void**)&ad1,  g_ad1);
    cudaGetSymbolAddress((void**)&out1, g_out1);
    cudaGetSymbolAddress((void**)&hx2,  g_hx2);
    cudaGetSymbolAddress((void**)&as2,  g_as2);
    cudaGetSymbolAddress((void**)&ad2,  g_ad2);
    cudaGetSymbolAddress((void**)&out2, g_out2);
    cudaGetSymbolAddress((void**)&u1,   g_u1);
    cudaGetSymbolAddress((void**)&u2,   g_u2);

    // ---- CSR build + attention vectors ----
    zero_detect_kernel<<<(NN + 255) / 256, 256>>>((const int*)ei);
    attvec_kernel<<<1, 192>>>(W1, att_src1, att_dst1, W2, att_src2, att_dst2);
    hist_kernel<<<EE / 256, 256>>>(ei);
    scan_kernel<<<1, 1024>>>();
    scatter_kernel<<<EE / 256, 256>>>(ei);

    // ---- layer 1 ----
    gemm_kernel<false><<<dim3((NN + 63) / 64, 1), 256>>>(x, W1, hx1, NN, FF, D1);
    gemv_kernel<64, false><<<NN / 8, 256>>>(x, u1, as1, ad1);
    agg_kernel<64><<<NN / 8, 256>>>(hx1, as1, ad1, bias1, out1);
    bnstats_kernel<<<400, D1>>>(out1, D1);
    bnfin_kernel<<<1, D1>>>(gamma1, beta1, D1);

    // ---- layer 2 (BN1+ReLU fused into gemm2/gemv2 A loads) ----
    gemm_kernel<true><<<dim3((NN + 63) / 64, 2), 256>>>(out1, W2, hx2, NN, D1, D2);
    gemv_kernel<128, true><<<NN / 8, 256>>>(out1, u2, as2, ad2);
    agg_kernel<128><<<NN / 8, 256>>>(hx2, as2, ad2, bias2, out2);
    bnstats_kernel<<<400, D2>>>(out2, D2);
    bnfin_kernel<<<1, D2>>>(gamma2, beta2, D2);
    bnapply_kernel<<<(NN * D2 + 255) / 256, 256>>>(out2, out, D2 - 1, NN * D2);
}

// round 4
// speedup vs baseline: 1.3230x; 1.3230x over previous
#include <cuda_runtime.h>
#include <cuda_fp16.h>
#include <cuda_bf16.h>
#include <math.h>

// ---------------------------------------------------------------------------
// GATLayers round 4: aggregate-then-transform.
//   out[n,h,:] = (sum_e alpha_e^h * x_in[src]) @ W_h + bias   (exact algebra)
// so we gather the *input* rows (half the bytes of hx rows) and never
// materialize hx. Scores come from u = W @ att vectors (exact, fp32 inputs).
// CSR: parallel 3-stage scan. GEMM/agg inner loops = proven round-2 forms.
// ---------------------------------------------------------------------------

constexpr int NN = 20000;
constexpr int EE = 640000;
constexpr int CB = (NN + 127) / 128;   // 157 scan blocks

// ------------------------------ scratch ------------------------------------
__device__ int    g_is64;
__device__ int    g_deg[NN];
__device__ int    g_rowptr[NN + 1];
__device__ int    g_rank[EE];
__device__ int    g_col[EE];
__device__ int    g_bsum[CB];
__device__ int    g_bpre[CB];
__device__ __half g_x16[NN * 64];      // fp16 copy of x
__device__ __half g_h16[NN * 128];     // fp16 relu(bn(out1))
__device__ float  g_y1[NN * 128];      // aggregated [N, 2, 64]
__device__ float  g_y2[NN * 256];      // aggregated [N, 2, 128]
__device__ float  g_out1[NN * 128];
__device__ float  g_out2[NN * 256];
__device__ float  g_as1[NN * 2];
__device__ float  g_ad1[NN * 2];
__device__ float  g_as2[NN * 2];
__device__ float  g_ad2[NN * 2];
__device__ float  g_part[200 * 2 * 256];
__device__ float  g_scale[256];
__device__ float  g_shift[256];
__device__ float4 g_u1[64];            // (us_h0, us_h1, ud_h0, ud_h1)
__device__ float4 g_u2[128];

// --------------------------- f32x2 helpers ----------------------------------
__device__ __forceinline__ unsigned long long pack2(float lo, float hi) {
    unsigned long long r;
    asm("mov.b64 %0, {%1, %2};" : "=l"(r)
        : "r"(__float_as_uint(lo)), "r"(__float_as_uint(hi)));
    return r;
}
__device__ __forceinline__ void unpk2(unsigned long long v, float& x, float& y) {
    unsigned a, b;
    asm("mov.b64 {%0, %1}, %2;" : "=r"(a), "=r"(b) : "l"(v));
    x = __uint_as_float(a); y = __uint_as_float(b);
}
__device__ __forceinline__ void ffma2(unsigned long long& d,
                                      unsigned long long a,
                                      unsigned long long b) {
    asm("fma.rn.f32x2 %0, %1, %2, %0;" : "+l"(d) : "l"(a), "l"(b));
}

// -------------------------- CSR construction -------------------------------
__global__ void prep_kernel(const int* __restrict__ ei32) {
    int i = blockIdx.x * blockDim.x + threadIdx.x;
    if (i < NN) g_deg[i] = 0;
    if (blockIdx.x == 0 && threadIdx.x < 32) {
        int lane = threadIdx.x;
        int a = ei32[2 * lane + 1];
        int b = ei32[2 * (lane + 32) + 1];
        unsigned m = __ballot_sync(0xffffffffu, (a | b) != 0);
        if (lane == 0) g_is64 = (m == 0) ? 1 : 0;
    }
}

__device__ __forceinline__ int edge_val(const void* ei, int idx, int is64) {
    if (is64) return (int)((const long long*)ei)[idx];
    return ((const int*)ei)[idx];
}

__global__ void hist_kernel(const void* __restrict__ ei) {
    int e = blockIdx.x * blockDim.x + threadIdx.x;
    if (e >= EE) return;
    int dst = edge_val(ei, EE + e, g_is64);
    g_rank[e] = atomicAdd(&g_deg[dst], 1);
}

__global__ void bsum_kernel() {
    const int t = threadIdx.x;            // 128
    const int i = blockIdx.x * 128 + t;
    int v = (i < NN) ? g_deg[i] : 0;
    #pragma unroll
    for (int o = 16; o; o >>= 1) v += __shfl_xor_sync(0xffffffffu, v, o);
    __shared__ int ws[4];
    if ((t & 31) == 0) ws[t >> 5] = v;
    __syncthreads();
    if (t == 0) g_bsum[blockIdx.x] = ws[0] + ws[1] + ws[2] + ws[3];
}

__global__ void bscan_kernel() {
    __shared__ int s[256];
    const int t = threadIdx.x;
    int v = (t < CB) ? g_bsum[t] : 0;
    s[t] = v;
    __syncthreads();
    for (int o = 1; o < 256; o <<= 1) {
        int u = (t >= o) ? s[t - o] : 0;
        __syncthreads();
        s[t] += u;
        __syncthreads();
    }
    if (t < CB) g_bpre[t] = s[t] - v;   // exclusive
}

__global__ void rowptr_kernel() {
    __shared__ int s[128];
    const int t = threadIdx.x;
    const int i = blockIdx.x * 128 + t;
    int d = (i < NN) ? g_deg[i] : 0;
    s[t] = d;
    __syncthreads();
    for (int o = 1; o < 128; o <<= 1) {
        int u = (t >= o) ? s[t - o] : 0;
        __syncthreads();
        s[t] += u;
        __syncthreads();
    }
    int incl = s[t];
    if (i < NN) g_rowptr[i] = g_bpre[blockIdx.x] + incl - d;
    if (i == NN - 1) g_rowptr[NN] = g_bpre[blockIdx.x] + incl;
}

__global__ void scatter_kernel(const void* __restrict__ ei) {
    int e = blockIdx.x * blockDim.x + threadIdx.x;
    if (e >= EE) return;
    int is64 = g_is64;
    int src = edge_val(ei, e, is64);
    int dst = edge_val(ei, EE + e, is64);
    g_col[g_rowptr[dst] + g_rank[e]] = src;
}

// ----------------------- attention vector precompute ------------------------
// u[f] = (W[f,:h0]·att_src_h0, W[f,:h1]·att_src_h1, same for att_dst)
__global__ void attvec_kernel(const float* __restrict__ W1,
                              const float* __restrict__ s1,
                              const float* __restrict__ d1,
                              const float* __restrict__ W2,
                              const float* __restrict__ s2,
                              const float* __restrict__ d2) {
    const int lane = threadIdx.x & 31;
    const int f = blockIdx.x * 8 + (threadIdx.x >> 5);  // 24 blocks * 8 warps
    float4 u = make_float4(0.f, 0.f, 0.f, 0.f);
    if (f < 64) {
        #pragma unroll
        for (int c = lane; c < 64; c += 32) {
            float w0 = W1[f * 128 + c], w1 = W1[f * 128 + 64 + c];
            u.x += w0 * s1[c];      u.y += w1 * s1[64 + c];
            u.z += w0 * d1[c];      u.w += w1 * d1[64 + c];
        }
    } else {
        int f2 = f - 64;
        #pragma unroll
        for (int c = lane; c < 128; c += 32) {
            float w0 = W2[f2 * 256 + c], w1 = W2[f2 * 256 + 128 + c];
            u.x += w0 * s2[c];      u.y += w1 * s2[128 + c];
            u.z += w0 * d2[c];      u.w += w1 * d2[128 + c];
        }
    }
    #pragma unroll
    for (int o = 16; o; o >>= 1) {
        u.x += __shfl_xor_sync(0xffffffffu, u.x, o);
        u.y += __shfl_xor_sync(0xffffffffu, u.y, o);
        u.z += __shfl_xor_sync(0xffffffffu, u.z, o);
        u.w += __shfl_xor_sync(0xffffffffu, u.w, o);
    }
    if (lane == 0) {
        if (f < 64) g_u1[f] = u;
        else        g_u2[f - 64] = u;
    }
}

// --------------------------- score GEMV (+fp16 copy) ------------------------
// Warp per node: (s0,s1,d0,d1) = sum_f v[f] * u[f]; also writes v as fp16.
// BN: v = relu(bn(A)) first (layer-2 input).
template <int K, bool BN>
__global__ __launch_bounds__(256) void gemv_kernel(
    const float* __restrict__ A, const float4* __restrict__ U,
    float* __restrict__ as_out, float* __restrict__ ad_out,
    __half* __restrict__ h16)
{
    const int lane = threadIdx.x & 31;
    const int warp = threadIdx.x >> 5;
    const int node = blockIdx.x * 8 + warp;
    float4 acc = make_float4(0.f, 0.f, 0.f, 0.f);
    #pragma unroll
    for (int f = lane; f < K; f += 32) {
        float v = A[(size_t)node * K + f];
        if (BN) { v = v * g_scale[f] + g_shift[f]; v = v > 0.f ? v : 0.f; }
        h16[(size_t)node * K + f] = __float2half_rn(v);
        float4 u = U[f];
        acc.x += v * u.x; acc.y += v * u.y;
        acc.z += v * u.z; acc.w += v * u.w;
    }
    #pragma unroll
    for (int o = 16; o; o >>= 1) {
        acc.x += __shfl_xor_sync(0xffffffffu, acc.x, o);
        acc.y += __shfl_xor_sync(0xffffffffu, acc.y, o);
        acc.z += __shfl_xor_sync(0xffffffffu, acc.z, o);
        acc.w += __shfl_xor_sync(0xffffffffu, acc.w, o);
    }
    if (lane == 0) {
        as_out[node * 2 + 0] = acc.x;
        as_out[node * 2 + 1] = acc.y;
        ad_out[node * 2 + 0] = acc.z;
        ad_out[node * 2 + 1] = acc.w;
    }
}

// ------------------- segment softmax + weighted aggregate ------------------
// Warp per node, both heads share the gathered row (F input features, fp16).
// Single pass: scores O(1), exp safe, p/z shift-invariant. Col prefetch only.
// y[n, h*F + f] = sum alpha^h * in[src, f]
template <int F>
__global__ __launch_bounds__(256) void agg_kernel(
    const __half* __restrict__ src16, const float* __restrict__ as,
    const float* __restrict__ ad, float* __restrict__ y)
{
    const int lane = threadIdx.x & 31;
    const int warp = threadIdx.x >> 5;
    const int node = blockIdx.x * 8 + warp;
    constexpr int V = F / 32;   // halves per lane: 2 or 4
    const int base = g_rowptr[node];
    const int deg = g_rowptr[node + 1] - base;
    const float2* as2 = (const float2*)as;
    const float2 adi = ((const float2*)ad)[node];

    float acc0[V], acc1[V];
    #pragma unroll
    for (int v = 0; v < V; v++) { acc0[v] = 0.f; acc1[v] = 0.f; }
    float z0, z1;

    auto accum = [&](const __half* row, float p0, float p1) {
        if constexpr (V == 2) {
            unsigned u = *(const unsigned*)row;
            float2 f = __half22float2(*(__half2*)&u);
            acc0[0] += p0 * f.x; acc0[1] += p0 * f.y;
            acc1[0] += p1 * f.x; acc1[1] += p1 * f.y;
        } else {
            uint2 u = *(const uint2*)row;
            float2 f0 = __half22float2(*(__half2*)&u.x);
            float2 f1 = __half22float2(*(__half2*)&u.y);
            acc0[0] += p0 * f0.x; acc0[1] += p0 * f0.y;
            acc0[2] += p0 * f1.x; acc0[3] += p0 * f1.y;
            acc1[0] += p1 * f0.x; acc1[1] += p1 * f0.y;
            acc1[2] += p1 * f1.x; acc1[3] += p1 * f1.y;
        }
    };

    {   // self loop
        float2 a = as2[node];
        float e0 = a.x + adi.x; e0 = e0 > 0.f ? e0 : 0.2f * e0;
        float e1 = a.y + adi.y; e1 = e1 > 0.f ? e1 : 0.2f * e1;
        float p0 = __expf(e0), p1 = __expf(e1);
        z0 = p0; z1 = p1;
        accum(src16 + (size_t)node * F + lane * V, p0, p1);
    }
    int s_next = (deg > 0) ? g_col[base] : 0;
    for (int j = 0; j < deg; j++) {
        int s = s_next;
        if (j + 1 < deg) s_next = g_col[base + j + 1];
        float2 a = as2[s];
        float e0 = a.x + adi.x; e0 = e0 > 0.f ? e0 : 0.2f * e0;
        float e1 = a.y + adi.y; e1 = e1 > 0.f ? e1 : 0.2f * e1;
        float p0 = __expf(e0), p1 = __expf(e1);
        z0 += p0; z1 += p1;
        accum(src16 + (size_t)s * F + lane * V, p0, p1);
    }

    const float i0 = 1.f / z0, i1 = 1.f / z1;
    float* yr = y + (size_t)node * 2 * F;
    if constexpr (V == 2) {
        *(float2*)(yr + lane * 2)     = make_float2(acc0[0] * i0, acc0[1] * i0);
        *(float2*)(yr + F + lane * 2) = make_float2(acc1[0] * i1, acc1[1] * i1);
    } else {
        *(float4*)(yr + lane * 4) =
            make_float4(acc0[0] * i0, acc0[1] * i0, acc0[2] * i0, acc0[3] * i0);
        *(float4*)(yr + F + lane * 4) =
            make_float4(acc1[0] * i1, acc1[1] * i1, acc1[2] * i1, acc1[3] * i1);
    }
}

// ------------------------------- GEMM --------------------------------------
// Per-head: C[:, cb:cb+TN] = A[:, cb:cb+K'] @ B[cb block] + bias. cb = by*TN.
// ld = full row width of A, B, C (2*TN). Round-2 proven inner loop.
template <int TN>
__global__ __launch_bounds__(256) void gemm_kernel(
    const float* __restrict__ A, const float* __restrict__ B,
    const float* __restrict__ bias, float* __restrict__ C,
    int M, int K, int ld)
{
    __shared__ float As[64 * 33];
    __shared__ float Bs[32 * TN];
    constexpr int CG = TN / 4;       // col groups: 16 or 32
    constexpr int RT = CG / 4;       // rows per thread: 4 or 8  (64/(256/CG))
    const int tid = threadIdx.x;
    const int tx = tid % CG;
    const int ty = tid / CG;
    const int row0 = blockIdx.x * 64;
    const int cb = blockIdx.y * TN;
    unsigned long long acc[RT][2];
    #pragma unroll
    for (int i = 0; i < RT; i++) { acc[i][0] = 0ull; acc[i][1] = 0ull; }

    for (int k0 = 0; k0 < K; k0 += 32) {
        #pragma unroll
        for (int i = 0; i < 8; i++) {
            int idx = tid + i * 256;
            int r = idx >> 5, c = idx & 31;
            int gr = row0 + r;
            As[r * 33 + c] = (gr < M) ? A[(size_t)gr * ld + cb + k0 + c] : 0.f;
        }
        #pragma unroll
        for (int i = 0; i < TN / 8; i++) {
            int idx = tid + i * 256;
            int r = idx / TN, c = idx % TN;
            Bs[idx] = B[(size_t)(k0 + r) * ld + cb + c];
        }
        __syncthreads();
        #pragma unroll
        for (int kk = 0; kk < 32; kk++) {
            ulonglong2 bv = *(const ulonglong2*)&Bs[kk * TN + tx * 4];
            #pragma unroll
            for (int i = 0; i < RT; i++) {
                float a = As[(ty * RT + i) * 33 + kk];
                unsigned long long aa = pack2(a, a);
                ffma2(acc[i][0], aa, bv.x);
                ffma2(acc[i][1], aa, bv.y);
            }
        }
        __syncthreads();
    }
    float4 bv4 = *(const float4*)&bias[cb + tx * 4];
    #pragma unroll
    for (int i = 0; i < RT; i++) {
        int gr = row0 + ty * RT + i;
        if (gr < M) {
            float c0, c1, c2, c3;
            unpk2(acc[i][0], c0, c1);
            unpk2(acc[i][1], c2, c3);
            *(float4*)&C[(size_t)gr * ld + cb + tx * 4] =
                make_float4(c0 + bv4.x, c1 + bv4.y, c2 + bv4.z, c3 + bv4.w);
        }
    }
}

// ------------------------------ batch norm ----------------------------------
__global__ void bnstats_kernel(const float* __restrict__ X, int COLS) {
    const int c = threadIdx.x;          // blockDim.x == COLS
    const int r0 = blockIdx.x * 100;    // 200 blocks * 100 rows
    float s = 0.f, q = 0.f;
    for (int r = r0; r < r0 + 100; r++) {
        float v = X[(size_t)r * COLS + c];
        s += v;
        q += v * v;
    }
    g_part[blockIdx.x * 2 * COLS + c] = s;
    g_part[blockIdx.x * 2 * COLS + COLS + c] = q;
}

__global__ void bnfin_kernel(const float* __restrict__ gamma,
                             const float* __restrict__ beta, int COLS) {
    const int c = threadIdx.x;
    float s = 0.f, q = 0.f;
    for (int b = 0; b < 200; b++) {
        s += g_part[b * 2 * COLS + c];
        q += g_part[b * 2 * COLS + COLS + c];
    }
    const float mu = s * (1.f / NN);
    const float var = q * (1.f / NN) - mu * mu;
    const float sc = gamma[c] * rsqrtf(var + 1e-5f);
    g_scale[c] = sc;
    g_shift[c] = beta[c] - mu * sc;
}

__global__ void bnapply_kernel(const float* __restrict__ X,
                               float* __restrict__ Y, int mask, int total) {
    int i = blockIdx.x * blockDim.x + threadIdx.x;
    if (i >= total) return;
    int c = i & mask;
    float y = X[i] * g_scale[c] + g_shift[c];
    Y[i] = y > 0.f ? y : 0.f;
}

// ------------------------------- launcher -----------------------------------
extern "C" void kernel_launch(void* const* d_in, const int* in_sizes, int n_in,
                              void* d_out, int out_size) {
    const float* x        = (const float*)d_in[0];
    const void*  ei       = d_in[1];
    const float* W1       = (const float*)d_in[2];
    const float* att_src1 = (const float*)d_in[3];
    const float* att_dst1 = (const float*)d_in[4];
    const float* bias1    = (const float*)d_in[5];
    const float* gamma1   = (const float*)d_in[6];
    const float* beta1    = (const float*)d_in[7];
    const float* W2       = (const float*)d_in[8];
    const float* att_src2 = (const float*)d_in[9];
    const float* att_dst2 = (const float*)d_in[10];
    const float* bias2    = (const float*)d_in[11];
    const float* gamma2   = (const float*)d_in[12];
    const float* beta2    = (const float*)d_in[13];
    float* out = (float*)d_out;

    __half *x16, *h16;
    float *y1, *y2, *out1, *out2, *as1, *ad1, *as2, *ad2;
    float4 *u1, *u2;
    cudaGetSymbolAddress((void**)&x16,  g_x16);
    cudaGetSymbolAddress((void**)&h16,  g_h16);
    cudaGetSymbolAddress((void**)&y1,   g_y1);
    cudaGetSymbolAddress((void**)&y2,   g_y2);
    cudaGetSymbolAddress((void**)&out1, g_out1);
    cudaGetSymbolAddress((void**)&out2, g_out2);
    cudaGetSymbolAddress((void**)&as1,  g_as1);
    cudaGetSymbolAddress((void**)&ad1,  g_ad1);
    cudaGetSymbolAddress((void**)&as2,  g_as2);
    cudaGetSymbolAddress((void**)&ad2,  g_ad2);
    cudaGetSymbolAddress((void**)&u1,   g_u1);
    cudaGetSymbolAddress((void**)&u2,   g_u2);

    // ---- CSR build + attention vectors ----
    prep_kernel<<<(NN + 255) / 256, 256>>>((const int*)ei);
    attvec_kernel<<<24, 256>>>(W1, att_src1, att_dst1, W2, att_src2, att_dst2);
    hist_kernel<<<EE / 256, 256>>>(ei);
    bsum_kernel<<<CB, 128>>>();
    bscan_kernel<<<1, 256>>>();
    rowptr_kernel<<<CB, 128>>>();
    scatter_kernel<<<EE / 256, 256>>>(ei);

    // ---- layer 1 ----
    gemv_kernel<64, false><<<NN / 8, 256>>>(x, u1, as1, ad1, x16);
    agg_kernel<64><<<NN / 8, 256>>>(x16, as1, ad1, y1);
    gemm_kernel<64><<<dim3((NN + 63) / 64, 2), 256>>>(y1, W1, bias1, out1,
                                                      NN, 64, 128);
    bnstats_kernel<<<200, 128>>>(out1, 128);
    bnfin_kernel<<<1, 128>>>(gamma1, beta1, 128);

    // ---- layer 2 ----
    gemv_kernel<128, true><<<NN / 8, 256>>>(out1, u2, as2, ad2, h16);
    agg_kernel<128><<<NN / 8, 256>>>(h16, as2, ad2, y2);
    gemm_kernel<128><<<dim3((NN + 63) / 64, 2), 256>>>(y2, W2, bias2, out2,
                                                       NN, 128, 256);
    bnstats_kernel<<<200, 256>>>(out2, 256);
    bnfin_kernel<<<1, 256>>>(gamma2, beta2, 256);
    bnapply_kernel<<<(NN * 256 + 255) / 256, 256>>>(out2, out, 255, NN * 256);
}

// round 5
// speedup vs baseline: 1.3939x; 1.0536x over previous
#include <cuda_runtime.h>
#include <cuda_fp16.h>
#include <cuda_bf16.h>
#include <math.h>

// ---------------------------------------------------------------------------
// GATLayers round 5: aggregate-then-transform + fused BN stats in GEMM
// epilogue + launch diet (17 -> 14 graph nodes) + agg row/score prefetch.
// ---------------------------------------------------------------------------

constexpr int NN = 20000;
constexpr int EE = 640000;
constexpr int CB = (NN + 255) / 256;   // 79 scan blocks (256 nodes each)
constexpr int GB = (NN + 63) / 64;     // 313 gemm row-blocks

// ------------------------------ scratch ------------------------------------
__device__ int    g_is64;
__device__ int    g_tick;              // last-block counter (self-resetting)
__device__ int    g_deg[NN];
__device__ int    g_rowptr[NN + 1];
__device__ int    g_rank[EE];
__device__ int    g_col[EE];
__device__ int    g_bsum[CB];
__device__ int    g_bpre[CB];
__device__ __half g_x16[NN * 64];      // fp16 copy of x
__device__ __half g_h16[NN * 128];     // fp16 relu(bn(out1))
__device__ float  g_y1[NN * 128];      // aggregated [N, 2, 64]
__device__ float  g_y2[NN * 256];      // aggregated [N, 2, 128]
__device__ float  g_out1[NN * 128];
__device__ float  g_out2[NN * 256];
__device__ float  g_as1[NN * 2];
__device__ float  g_ad1[NN * 2];
__device__ float  g_as2[NN * 2];
__device__ float  g_ad2[NN * 2];
__device__ float  g_part[GB * 2 * 256];
__device__ float  g_scale[256];
__device__ float  g_shift[256];
__device__ float4 g_u1[64];            // (us_h0, us_h1, ud_h0, ud_h1)
__device__ float4 g_u2[128];

// --------------------------- f32x2 helpers ----------------------------------
__device__ __forceinline__ unsigned long long pack2(float lo, float hi) {
    unsigned long long r;
    asm("mov.b64 %0, {%1, %2};" : "=l"(r)
        : "r"(__float_as_uint(lo)), "r"(__float_as_uint(hi)));
    return r;
}
__device__ __forceinline__ void unpk2(unsigned long long v, float& x, float& y) {
    unsigned a, b;
    asm("mov.b64 {%0, %1}, %2;" : "=r"(a), "=r"(b) : "l"(v));
    x = __uint_as_float(a); y = __uint_as_float(b);
}
__device__ __forceinline__ void ffma2(unsigned long long& d,
                                      unsigned long long a,
                                      unsigned long long b) {
    asm("fma.rn.f32x2 %0, %1, %2, %0;" : "+l"(d) : "l"(a), "l"(b));
}

// ----------------- prep: deg zero + dtype detect + attvec -------------------
// blocks [0,79): zero g_deg (+is64 detect in block 0)
// blocks [79,103): u[f] = (W[f]·att_src_h0, h1, att_dst_h0, h1)
__global__ __launch_bounds__(256) void prep_kernel(
    const int* __restrict__ ei32,
    const float* __restrict__ W1, const float* __restrict__ s1,
    const float* __restrict__ d1,
    const float* __restrict__ W2, const float* __restrict__ s2,
    const float* __restrict__ d2)
{
    const int bx = blockIdx.x;
    if (bx < 79) {
        int i = bx * 256 + threadIdx.x;
        if (i < NN) g_deg[i] = 0;
        if (bx == 0 && threadIdx.x < 32) {
            int lane = threadIdx.x;
            int a = ei32[2 * lane + 1];
            int b = ei32[2 * (lane + 32) + 1];
            unsigned m = __ballot_sync(0xffffffffu, (a | b) != 0);
            if (lane == 0) g_is64 = (m == 0) ? 1 : 0;
        }
        return;
    }
    const int lane = threadIdx.x & 31;
    const int f = (bx - 79) * 8 + (threadIdx.x >> 5);   // 0..191
    float4 u = make_float4(0.f, 0.f, 0.f, 0.f);
    if (f < 64) {
        #pragma unroll
        for (int c = lane; c < 64; c += 32) {
            float w0 = W1[f * 128 + c], w1 = W1[f * 128 + 64 + c];
            u.x += w0 * s1[c];      u.y += w1 * s1[64 + c];
            u.z += w0 * d1[c];      u.w += w1 * d1[64 + c];
        }
    } else {
        int f2 = f - 64;
        #pragma unroll
        for (int c = lane; c < 128; c += 32) {
            float w0 = W2[f2 * 256 + c], w1 = W2[f2 * 256 + 128 + c];
            u.x += w0 * s2[c];      u.y += w1 * s2[128 + c];
            u.z += w0 * d2[c];      u.w += w1 * d2[128 + c];
        }
    }
    #pragma unroll
    for (int o = 16; o; o >>= 1) {
        u.x += __shfl_xor_sync(0xffffffffu, u.x, o);
        u.y += __shfl_xor_sync(0xffffffffu, u.y, o);
        u.z += __shfl_xor_sync(0xffffffffu, u.z, o);
        u.w += __shfl_xor_sync(0xffffffffu, u.w, o);
    }
    if (lane == 0) {
        if (f < 64) g_u1[f] = u;
        else        g_u2[f - 64] = u;
    }
}

// -------------------------- CSR construction -------------------------------
__device__ __forceinline__ int edge_val(const void* ei, int idx, int is64) {
    if (is64) return (int)((const long long*)ei)[idx];
    return ((const int*)ei)[idx];
}

__global__ void hist_kernel(const void* __restrict__ ei) {
    int e = blockIdx.x * blockDim.x + threadIdx.x;
    if (e >= EE) return;
    int dst = edge_val(ei, EE + e, g_is64);
    g_rank[e] = atomicAdd(&g_deg[dst], 1);
}

// block sums of deg (256/node block) + last-block exclusive scan of sums
__global__ __launch_bounds__(256) void bsum_scan_kernel() {
    const int t = threadIdx.x;
    const int i = blockIdx.x * 256 + t;
    int v = (i < NN) ? g_deg[i] : 0;
    #pragma unroll
    for (int o = 16; o; o >>= 1) v += __shfl_xor_sync(0xffffffffu, v, o);
    __shared__ int ws[8];
    if ((t & 31) == 0) ws[t >> 5] = v;
    __syncthreads();
    if (t == 0) {
        int s = 0;
        #pragma unroll
        for (int w = 0; w < 8; w++) s += ws[w];
        g_bsum[blockIdx.x] = s;
        __threadfence();
    }
    __shared__ int amLast;
    if (t == 0) amLast = (atomicAdd(&g_tick, 1) == (int)gridDim.x - 1);
    __syncthreads();
    if (!amLast) return;
    __shared__ int s[256];
    int b = (t < CB) ? g_bsum[t] : 0;
    s[t] = b;
    __syncthreads();
    for (int o = 1; o < 256; o <<= 1) {
        int u = (t >= o) ? s[t - o] : 0;
        __syncthreads();
        s[t] += u;
        __syncthreads();
    }
    if (t < CB) g_bpre[t] = s[t] - b;   // exclusive
    if (t == 0) g_tick = 0;             // reset for next replay
}

__global__ __launch_bounds__(256) void rowptr_kernel() {
    __shared__ int s[256];
    const int t = threadIdx.x;
    const int i = blockIdx.x * 256 + t;
    int d = (i < NN) ? g_deg[i] : 0;
    s[t] = d;
    __syncthreads();
    for (int o = 1; o < 256; o <<= 1) {
        int u = (t >= o) ? s[t - o] : 0;
        __syncthreads();
        s[t] += u;
        __syncthreads();
    }
    int incl = s[t];
    if (i < NN) g_rowptr[i] = g_bpre[blockIdx.x] + incl - d;
    if (i == NN - 1) g_rowptr[NN] = g_bpre[blockIdx.x] + incl;
}

__global__ void scatter_kernel(const void* __restrict__ ei) {
    int e = blockIdx.x * blockDim.x + threadIdx.x;
    if (e >= EE) return;
    int is64 = g_is64;
    int src = edge_val(ei, e, is64);
    int dst = edge_val(ei, EE + e, is64);
    g_col[g_rowptr[dst] + g_rank[e]] = src;
}

// --------------------------- score GEMV (+fp16 copy) ------------------------
template <int K, bool BN>
__global__ __launch_bounds__(256) void gemv_kernel(
    const float* __restrict__ A, const float4* __restrict__ U,
    float* __restrict__ as_out, float* __restrict__ ad_out,
    __half* __restrict__ h16)
{
    const int lane = threadIdx.x & 31;
    const int warp = threadIdx.x >> 5;
    const int node = blockIdx.x * 8 + warp;
    float4 acc = make_float4(0.f, 0.f, 0.f, 0.f);
    #pragma unroll
    for (int f = lane; f < K; f += 32) {
        float v = A[(size_t)node * K + f];
        if (BN) { v = v * g_scale[f] + g_shift[f]; v = v > 0.f ? v : 0.f; }
        h16[(size_t)node * K + f] = __float2half_rn(v);
        float4 u = U[f];
        acc.x += v * u.x; acc.y += v * u.y;
        acc.z += v * u.z; acc.w += v * u.w;
    }
    #pragma unroll
    for (int o = 16; o; o >>= 1) {
        acc.x += __shfl_xor_sync(0xffffffffu, acc.x, o);
        acc.y += __shfl_xor_sync(0xffffffffu, acc.y, o);
        acc.z += __shfl_xor_sync(0xffffffffu, acc.z, o);
        acc.w += __shfl_xor_sync(0xffffffffu, acc.w, o);
    }
    if (lane == 0) {
        as_out[node * 2 + 0] = acc.x;
        as_out[node * 2 + 1] = acc.y;
        ad_out[node * 2 + 0] = acc.z;
        ad_out[node * 2 + 1] = acc.w;
    }
}

// ------------------- segment softmax + weighted aggregate ------------------
// Warp per node, both heads. Single pass; prefetch col, score and row.
template <int F>
__global__ __launch_bounds__(256) void agg_kernel(
    const __half* __restrict__ src16, const float* __restrict__ as,
    const float* __restrict__ ad, float* __restrict__ y)
{
    const int lane = threadIdx.x & 31;
    const int warp = threadIdx.x >> 5;
    const int node = blockIdx.x * 8 + warp;
    constexpr int V = F / 32;   // halves per lane: 2 or 4
    using RowT = typename std::conditional<V == 2, unsigned, uint2>::type;
    const int base = g_rowptr[node];
    const int deg = g_rowptr[node + 1] - base;
    const float2* as2 = (const float2*)as;
    const float2 adi = ((const float2*)ad)[node];

    float acc0[V], acc1[V];
    #pragma unroll
    for (int v = 0; v < V; v++) { acc0[v] = 0.f; acc1[v] = 0.f; }
    float z0, z1;

    auto accum = [&](RowT u, float p0, float p1) {
        if constexpr (V == 2) {
            float2 f = __half22float2(*(__half2*)&u);
            acc0[0] += p0 * f.x; acc0[1] += p0 * f.y;
            acc1[0] += p1 * f.x; acc1[1] += p1 * f.y;
        } else {
            float2 f0 = __half22float2(*(__half2*)&u.x);
            float2 f1 = __half22float2(*(__half2*)&u.y);
            acc0[0] += p0 * f0.x; acc0[1] += p0 * f0.y;
            acc0[2] += p0 * f1.x; acc0[3] += p0 * f1.y;
            acc1[0] += p1 * f0.x; acc1[1] += p1 * f0.y;
            acc1[2] += p1 * f1.x; acc1[3] += p1 * f1.y;
        }
    };

    {   // self loop
        float2 a = as2[node];
        float e0 = a.x + adi.x; e0 = e0 > 0.f ? e0 : 0.2f * e0;
        float e1 = a.y + adi.y; e1 = e1 > 0.f ? e1 : 0.2f * e1;
        float p0 = __expf(e0), p1 = __expf(e1);
        z0 = p0; z1 = p1;
        RowT u = *(const RowT*)(src16 + (size_t)node * F + lane * V);
        accum(u, p0, p1);
    }
    if (deg > 0) {
        int s = g_col[base];
        float2 a_n = as2[s];
        RowT u_n = *(const RowT*)(src16 + (size_t)s * F + lane * V);
        for (int j = 0; j < deg; j++) {
            float2 a = a_n;
            RowT u = u_n;
            if (j + 1 < deg) {
                int s2 = g_col[base + j + 1];
                a_n = as2[s2];
                u_n = *(const RowT*)(src16 + (size_t)s2 * F + lane * V);
            }
            float e0 = a.x + adi.x; e0 = e0 > 0.f ? e0 : 0.2f * e0;
            float e1 = a.y + adi.y; e1 = e1 > 0.f ? e1 : 0.2f * e1;
            float p0 = __expf(e0), p1 = __expf(e1);
            z0 += p0; z1 += p1;
            accum(u, p0, p1);
        }
    }

    const float i0 = 1.f / z0, i1 = 1.f / z1;
    float* yr = y + (size_t)node * 2 * F;
    if constexpr (V == 2) {
        *(float2*)(yr + lane * 2)     = make_float2(acc0[0] * i0, acc0[1] * i0);
        *(float2*)(yr + F + lane * 2) = make_float2(acc1[0] * i1, acc1[1] * i1);
    } else {
        *(float4*)(yr + lane * 4) =
            make_float4(acc0[0] * i0, acc0[1] * i0, acc0[2] * i0, acc0[3] * i0);
        *(float4*)(yr + F + lane * 4) =
            make_float4(acc1[0] * i1, acc1[1] * i1, acc1[2] * i1, acc1[3] * i1);
    }
}

// ------------------------------- GEMM + BN stats ----------------------------
// Per-head: C[:, cb:cb+TN] = A[:, cb:cb+K'] @ B[cb block] + bias, cb = by*TN,
// ld = 2*TN. Epilogue: per-block column sum/sumsq -> g_part (for BN).
template <int TN>
__global__ __launch_bounds__(256) void gemm_kernel(
    const float* __restrict__ A, const float* __restrict__ B,
    const float* __restrict__ bias, float* __restrict__ C,
    int M, int K, int ld)
{
    __shared__ float As[64 * 33];
    __shared__ float Bs[32 * TN];
    constexpr int CG = TN / 4;       // col groups: 16 or 32
    constexpr int RT = CG / 4;       // rows per thread: 4 or 8
    constexpr int TY = 256 / CG;     // thread rows: 16 or 8
    const int tid = threadIdx.x;
    const int tx = tid % CG;
    const int ty = tid / CG;
    const int row0 = blockIdx.x * 64;
    const int cb = blockIdx.y * TN;
    unsigned long long acc[RT][2];
    #pragma unroll
    for (int i = 0; i < RT; i++) { acc[i][0] = 0ull; acc[i][1] = 0ull; }

    for (int k0 = 0; k0 < K; k0 += 32) {
        #pragma unroll
        for (int i = 0; i < 8; i++) {
            int idx = tid + i * 256;
            int r = idx >> 5, c = idx & 31;
            int gr = row0 + r;
            As[r * 33 + c] = (gr < M) ? A[(size_t)gr * ld + cb + k0 + c] : 0.f;
        }
        #pragma unroll
        for (int i = 0; i < TN / 8; i++) {
            int idx = tid + i * 256;
            int r = idx / TN, c = idx % TN;
            Bs[idx] = B[(size_t)(k0 + r) * ld + cb + c];
        }
        __syncthreads();
        #pragma unroll
        for (int kk = 0; kk < 32; kk++) {
            ulonglong2 bv = *(const ulonglong2*)&Bs[kk * TN + tx * 4];
            #pragma unroll
            for (int i = 0; i < RT; i++) {
                float a = As[(ty * RT + i) * 33 + kk];
                unsigned long long aa = pack2(a, a);
                ffma2(acc[i][0], aa, bv.x);
                ffma2(acc[i][1], aa, bv.y);
            }
        }
        __syncthreads();
    }
    float4 bv4 = *(const float4*)&bias[cb + tx * 4];
    float ls[4] = {0.f, 0.f, 0.f, 0.f};
    float lq[4] = {0.f, 0.f, 0.f, 0.f};
    #pragma unroll
    for (int i = 0; i < RT; i++) {
        int gr = row0 + ty * RT + i;
        if (gr < M) {
            float c0, c1, c2, c3;
            unpk2(acc[i][0], c0, c1);
            unpk2(acc[i][1], c2, c3);
            c0 += bv4.x; c1 += bv4.y; c2 += bv4.z; c3 += bv4.w;
            *(float4*)&C[(size_t)gr * ld + cb + tx * 4] =
                make_float4(c0, c1, c2, c3);
            ls[0] += c0; ls[1] += c1; ls[2] += c2; ls[3] += c3;
            lq[0] += c0 * c0; lq[1] += c1 * c1;
            lq[2] += c2 * c2; lq[3] += c3 * c3;
        }
    }
    // column-wise reduce across TY thread rows via smem (reuse As/Bs)
    #pragma unroll
    for (int j = 0; j < 4; j++) {
        As[ty * TN + tx * 4 + j] = ls[j];
        Bs[ty * TN + tx * 4 + j] = lq[j];
    }
    __syncthreads();
    if (tid < TN) {
        float s = 0.f, q = 0.f;
        #pragma unroll
        for (int yy = 0; yy < TY; yy++) {
            s += As[yy * TN + tid];
            q += Bs[yy * TN + tid];
        }
        int col = cb + tid;
        g_part[blockIdx.x * 2 * ld + col] = s;
        g_part[blockIdx.x * 2 * ld + ld + col] = q;
    }
}

// --------------------------- BN finalize ------------------------------------
// grid COLS/64, block (64, 8): reduce GB partials per column.
__global__ void bnfin_kernel(const float* __restrict__ gamma,
                             const float* __restrict__ beta, int COLS) {
    const int tx = threadIdx.x;   // 64
    const int tyy = threadIdx.y;  // 8
    const int c = blockIdx.x * 64 + tx;
    float s = 0.f, q = 0.f;
    for (int b = tyy; b < GB; b += 8) {
        s += g_part[b * 2 * COLS + c];
        q += g_part[b * 2 * COLS + COLS + c];
    }
    __shared__ float ss[8][64], sq[8][64];
    ss[tyy][tx] = s; sq[tyy][tx] = q;
    __syncthreads();
    if (tyy == 0) {
        #pragma unroll
        for (int yy = 1; yy < 8; yy++) { s += ss[yy][tx]; q += sq[yy][tx]; }
        const float mu = s * (1.f / NN);
        const float var = q * (1.f / NN) - mu * mu;
        const float sc = gamma[c] * rsqrtf(var + 1e-5f);
        g_scale[c] = sc;
        g_shift[c] = beta[c] - mu * sc;
    }
}

__global__ void bnapply_kernel(const float* __restrict__ X,
                               float* __restrict__ Y, int mask, int total) {
    int i = blockIdx.x * blockDim.x + threadIdx.x;
    if (i >= total) return;
    int c = i & mask;
    float y = X[i] * g_scale[c] + g_shift[c];
    Y[i] = y > 0.f ? y : 0.f;
}

// ------------------------------- launcher -----------------------------------
extern "C" void kernel_launch(void* const* d_in, const int* in_sizes, int n_in,
                              void* d_out, int out_size) {
    const float* x        = (const float*)d_in[0];
    const void*  ei       = d_in[1];
    const float* W1       = (const float*)d_in[2];
    const float* att_src1 = (const float*)d_in[3];
    const float* att_dst1 = (const float*)d_in[4];
    const float* bias1    = (const float*)d_in[5];
    const float* gamma1   = (const float*)d_in[6];
    const float* beta1    = (const float*)d_in[7];
    const float* W2       = (const float*)d_in[8];
    const float* att_src2 = (const float*)d_in[9];
    const float* att_dst2 = (const float*)d_in[10];
    const float* bias2    = (const float*)d_in[11];
    const float* gamma2   = (const float*)d_in[12];
    const float* beta2    = (const float*)d_in[13];
    float* out = (float*)d_out;

    __half *x16, *h16;
    float *y1, *y2, *out1, *out2, *as1, *ad1, *as2, *ad2;
    float4 *u1, *u2;
    cudaGetSymbolAddress((void**)&x16,  g_x16);
    cudaGetSymbolAddress((void**)&h16,  g_h16);
    cudaGetSymbolAddress((void**)&y1,   g_y1);
    cudaGetSymbolAddress((void**)&y2,   g_y2);
    cudaGetSymbolAddress((void**)&out1, g_out1);
    cudaGetSymbolAddress((void**)&out2, g_out2);
    cudaGetSymbolAddress((void**)&as1,  g_as1);
    cudaGetSymbolAddress((void**)&ad1,  g_ad1);
    cudaGetSymbolAddress((void**)&as2,  g_as2);
    cudaGetSymbolAddress((void**)&ad2,  g_ad2);
    cudaGetSymbolAddress((void**)&u1,   g_u1);
    cudaGetSymbolAddress((void**)&u2,   g_u2);

    // ---- CSR build + attention vectors ----
    prep_kernel<<<103, 256>>>((const int*)ei, W1, att_src1, att_dst1,
                              W2, att_src2, att_dst2);
    hist_kernel<<<EE / 256, 256>>>(ei);
    bsum_scan_kernel<<<CB, 256>>>();
    rowptr_kernel<<<CB, 256>>>();
    scatter_kernel<<<EE / 256, 256>>>(ei);

    // ---- layer 1 ----
    gemv_kernel<64, false><<<NN / 8, 256>>>(x, u1, as1, ad1, x16);
    agg_kernel<64><<<NN / 8, 256>>>(x16, as1, ad1, y1);
    gemm_kernel<64><<<dim3(GB, 2), 256>>>(y1, W1, bias1, out1, NN, 64, 128);
    bnfin_kernel<<<2, dim3(64, 8)>>>(gamma1, beta1, 128);

    // ---- layer 2 ----
    gemv_kernel<128, true><<<NN / 8, 256>>>(out1, u2, as2, ad2, h16);
    agg_kernel<128><<<NN / 8, 256>>>(h16, as2, ad2, y2);
    gemm_kernel<128><<<dim3(GB, 2), 256>>>(y2, W2, bias2, out2, NN, 128, 256);
    bnfin_kernel<<<4, dim3(64, 8)>>>(gamma2, beta2, 256);
    bnapply_kernel<<<(NN * 256 + 255) / 256, 256>>>(out2, out, 255, NN * 256);
}